// round 12
// baseline (speedup 1.0000x reference)
#include <cuda_runtime.h>
#include <cuda_fp16.h>
#include <cstdint>

// ---------------------------------------------------------------------------
// y[b,o] = sum_i x[b,i] * lut[widx[o,i]] + bias[o]
//   B=32, IN=8192, OUT=16384 ; lut affine: lut[c] = lut[0] + c*(lut[1]-lut[0])
//
// Exact-precision fp16 MMA scheme (validated R3..R11):
//   A = (idx-128) exact in fp16 via (0x6400|idx) -> 1024+idx, HSUB2 1152.
//   x = x_hi + x_lo fp16 split; 2x mma.m16n8k16.f16, fp32 accum.
//   out preinit = bias[o] + c0*sumx[b]; GEMM adds sc*acc atomically.
//
// R12: W smem staging DELETED. W comes straight to registers in fragment
// layout via ld.global.L1::evict_first.L2::256B.v4.u32, double-buffered one
// k16-grp ahead; DRAM->L2 leg covered by explicit prefetch.global.L2 issued
// 8 grps (~2KB) ahead (one 256B window per 4 grps per row). Crossbar traffic
// drops ~64% (only x staging remains), smem falls to 36KB/CTA, warps fully
// decoupled from the LDGSTS pipe. 2 CTAs/SM, persistent 296 CTAs, atomic
// flush + fused prep unchanged.
// ---------------------------------------------------------------------------

#define PB       32
#define PIN      8192
#define POUT     16384
#define NTHREADS 256
#define NCTA     296                      // 2 CTAs per SM
#define TROWS    256                      // rows per tile
#define NUNIT    2048                     // 64 tiles * 32 k256-chunks
#define XSTG_U4  1152                     // 32 batch * 36 pitch (uint4)
#define SMEM_BYTES (2 * XSTG_U4 * 16)     // 36864

__device__ __forceinline__ uint4 ldg_w(const void* p) {
    uint4 v;
    asm volatile("ld.global.L1::evict_first.L2::256B.v4.u32 {%0,%1,%2,%3}, [%4];"
                 : "=r"(v.x), "=r"(v.y), "=r"(v.z), "=r"(v.w) : "l"(p));
    return v;
}

__device__ __forceinline__ void prefetchL2(const void* p) {
    asm volatile("prefetch.global.L2 [%0];" :: "l"(p));
}

__device__ __forceinline__ void mma_f16(float* c,
                                        uint32_t a0, uint32_t a1, uint32_t a2, uint32_t a3,
                                        uint32_t b0, uint32_t b1) {
    asm volatile(
        "mma.sync.aligned.m16n8k16.row.col.f32.f16.f16.f32 "
        "{%0,%1,%2,%3}, {%4,%5,%6,%7}, {%8,%9}, {%0,%1,%2,%3};"
        : "+f"(c[0]), "+f"(c[1]), "+f"(c[2]), "+f"(c[3])
        : "r"(a0), "r"(a1), "r"(a2), "r"(a3), "r"(b0), "r"(b1));
}

// two int8 codes -> packed half2 of EXACT (idx-128)
__device__ __forceinline__ uint32_t packA(uint32_t i0, uint32_t i1, uint32_t off2) {
    uint32_t r = 0x64006400u | i0 | (i1 << 16);
    __half2 h = __hsub2(*reinterpret_cast<__half2*>(&r),
                        *reinterpret_cast<const __half2*>(&off2));
    return *reinterpret_cast<uint32_t*>(&h);
}

__device__ __forceinline__ uint4 split_x4(float4 v) {
    __half2 h0 = __floats2half2_rn(v.x, v.y);
    __half2 h1 = __floats2half2_rn(v.z, v.w);
    float2 f0 = __half22float2(h0);
    float2 f1 = __half22float2(h1);
    __half2 l0 = __floats2half2_rn(v.x - f0.x, v.y - f0.y);
    __half2 l1 = __floats2half2_rn(v.z - f1.x, v.w - f1.y);
    uint4 s;
    s.x = *reinterpret_cast<uint32_t*>(&h0);
    s.y = *reinterpret_cast<uint32_t*>(&h1);
    s.z = *reinterpret_cast<uint32_t*>(&l0);
    s.w = *reinterpret_cast<uint32_t*>(&l1);
    return s;
}

// ---- fused prep: out[b, o] = bias[o] + c0*sumx[b] (grid = 4*PB) ----
__global__ void prep_out_kernel(const float* __restrict__ x,
                                const float* __restrict__ lut,
                                const float* __restrict__ bias,
                                float* __restrict__ out) {
    __shared__ float red[8];
    const int b       = blockIdx.x >> 2;
    const int quarter = blockIdx.x & 3;

    const float4* xr = reinterpret_cast<const float4*>(x + (size_t)b * PIN);
    float s = 0.0f;
    #pragma unroll
    for (int j = 0; j < (PIN / 4) / 256; ++j) {
        float4 v = __ldg(xr + threadIdx.x + 256 * j);
        s += (v.x + v.y) + (v.z + v.w);
    }
    #pragma unroll
    for (int o = 16; o; o >>= 1) s += __shfl_xor_sync(0xFFFFFFFFu, s, o);
    if ((threadIdx.x & 31) == 0) red[threadIdx.x >> 5] = s;
    __syncthreads();
    {
        float t = red[0];
        #pragma unroll
        for (int k = 1; k < 8; ++k) t += red[k];
        s = t;                                             // deterministic order
    }

    const float l0 = __ldg(lut);
    const float sc = __ldg(lut + 1) - l0;
    const float c0 = fmaf(128.0f, sc, l0);
    const float addv = c0 * s;

    const int obase = quarter * (POUT / 4);
    const float4* bq = reinterpret_cast<const float4*>(bias + obase);
    float4* oq = reinterpret_cast<float4*>(out + (size_t)b * POUT + obase);
    #pragma unroll
    for (int j = 0; j < (POUT / 4) / 4 / 256; ++j) {
        float4 bv = __ldg(bq + threadIdx.x + 256 * j);
        bv.x += addv; bv.y += addv; bv.z += addv; bv.w += addv;
        oq[threadIdx.x + 256 * j] = bv;
    }
}

__global__ void __launch_bounds__(NTHREADS, 2)
linear_int8_mma_kernel(const float* __restrict__ x,
                       const float* __restrict__ lut,
                       const float* __restrict__ bias,
                       const int*   __restrict__ widx,
                       float*       __restrict__ out) {
    extern __shared__ __align__(16) uint4 xs[];   // x: 2 x 1152 uint4

    const int tid  = threadIdx.x;
    const int w    = tid >> 5;
    const int lane = tid & 31;
    const int g    = lane >> 2;       // fragment group: A row / B col
    const int q    = lane & 3;        // fragment k-slot

    const float l0 = __ldg(lut);
    const float sc = __ldg(lut + 1) - l0;
    const uint32_t off1152 = 0x64806480u;   // half2(1152,1152)

    // ---- this CTA's flat k256-chunk range [s, e) ----
    const int s = (int)(((unsigned)blockIdx.x * NUNIT) / NCTA);
    const int e = (int)((((unsigned)blockIdx.x + 1) * NUNIT) / NCTA);
    const int gEnd = e * 16;                   // k16-grp end

    // warp covers rows rowsub + {0,8,16,24} of the 256-row tile
    const int rowsub = w * 32 + g;
    const char* wr0 = reinterpret_cast<const char*>(widx)
                      + (size_t)rowsub * PIN * 4 + (size_t)q * 16;
    const size_t TILESTRIDE = (size_t)TROWS * PIN * 4;    // 8MB per tile
    const size_t J8 = (size_t)8 * PIN * 4;                // +8 rows

    // W address of k16-grp gg for this thread's base row
    auto waddr = [&](int gg) -> const char* {
        const int cu  = gg >> 4;
        const int k16 = (cu & 31) * 16 + (gg & 15);
        return wr0 + (size_t)(cu >> 5) * TILESTRIDE + (size_t)k16 * 64;
    };

    float acc[2][4][4];
    #pragma unroll
    for (int h = 0; h < 2; ++h)
        #pragma unroll
        for (int t = 0; t < 4; ++t)
            #pragma unroll
            for (int i = 0; i < 4; ++i) acc[h][t][i] = 0.0f;

    const int gStart = s * 16;

    // ---- prologue: prefetch first 3 windows, preload grp gStart ----
    #pragma unroll
    for (int pw = 0; pw < 3; ++pw) {
        const char* pp = waddr(gStart + 4 * pw);
        #pragma unroll
        for (int j = 0; j < 4; ++j) prefetchL2(pp + (size_t)j * J8);
    }
    uint4 cw[4];
    {
        const char* p = waddr(gStart);
        #pragma unroll
        for (int j = 0; j < 4; ++j) cw[j] = ldg_w(p + (size_t)j * J8);
    }

    // ---- stage x: half 0 of unit s ----
    const float4* xg = reinterpret_cast<const float4*>(x);
    float4 xr[4];
    {
        const int kb4 = (s & 31) * 64;
        #pragma unroll
        for (int j = 0; j < 4; ++j)
            xr[j] = __ldg(xg + (size_t)(w + 8 * j) * (PIN / 4) + kb4 + lane);
        uint4* db = xs + ((s * 2) & 1) * XSTG_U4;
        #pragma unroll
        for (int j = 0; j < 4; ++j)
            db[(w + 8 * j) * 36 + lane] = split_x4(xr[j]);
    }
    __syncthreads();

    int cur_tile = s >> 5;

    for (int c = s; c < e; ++c) {
        const int t_tile = c >> 5;
        if (t_tile != cur_tile) {
            #pragma unroll
            for (int h = 0; h < 2; ++h) {
                const int o0 = cur_tile * TROWS + rowsub + 16 * h;
                #pragma unroll
                for (int t = 0; t < 4; ++t) {
                    const int n0 = 8 * t + 2 * q;
                    atomicAdd(&out[(size_t)n0 * POUT + o0],           sc * acc[h][t][0]);
                    atomicAdd(&out[(size_t)(n0 + 1) * POUT + o0],     sc * acc[h][t][1]);
                    atomicAdd(&out[(size_t)n0 * POUT + o0 + 8],       sc * acc[h][t][2]);
                    atomicAdd(&out[(size_t)(n0 + 1) * POUT + o0 + 8], sc * acc[h][t][3]);
                    acc[h][t][0] = acc[h][t][1] = acc[h][t][2] = acc[h][t][3] = 0.0f;
                }
            }
            cur_tile = t_tile;
        }

        #pragma unroll
        for (int h = 0; h < 2; ++h) {
            const uint4* xb = xs + ((c * 2 + h) & 1) * XSTG_U4;

            // prefetch next k128 half of x into registers
            const int nexthalf = c * 2 + h + 1;
            const bool more = nexthalf < e * 2;
            if (more) {
                const int cn = nexthalf >> 1, hn = nexthalf & 1;
                const int kb4 = (cn & 31) * 64 + hn * 32;
                #pragma unroll
                for (int j = 0; j < 4; ++j)
                    xr[j] = __ldg(xg + (size_t)(w + 8 * j) * (PIN / 4) + kb4 + lane);
            }

            const int gbase = c * 16 + h * 8;
            #pragma unroll
            for (int st = 0; st < 8; ++st) {
                const int gg = gbase + st;

                // L2 prefetch 8 grps ahead (one 256B window per 4 grps)
                if ((gg & 3) == 0 && gg + 8 < gEnd) {
                    const char* pp = waddr(gg + 8);
                    #pragma unroll
                    for (int j = 0; j < 4; ++j) prefetchL2(pp + (size_t)j * J8);
                }

                // register double-buffer: load grp gg+1 (L2 hit)
                uint4 cwN[4];
                if (gg + 1 < gEnd) {
                    const char* p = waddr(gg + 1);
                    #pragma unroll
                    for (int j = 0; j < 4; ++j) cwN[j] = ldg_w(p + (size_t)j * J8);
                }

                // ---- dequant current grp ----
                const uint32_t A00 = packA(cw[0].x, cw[0].y, off1152);
                const uint32_t A02 = packA(cw[0].z, cw[0].w, off1152);
                const uint32_t A01 = packA(cw[1].x, cw[1].y, off1152);
                const uint32_t A03 = packA(cw[1].z, cw[1].w, off1152);
                const uint32_t A10 = packA(cw[2].x, cw[2].y, off1152);
                const uint32_t A12 = packA(cw[2].z, cw[2].w, off1152);
                const uint32_t A11 = packA(cw[3].x, cw[3].y, off1152);
                const uint32_t A13 = packA(cw[3].z, cw[3].w, off1152);

                // ---- x fragments + MMA (x shared by both m16 tiles) ----
                const int entry = st * 4 + q;
                #pragma unroll
                for (int t = 0; t < 4; ++t) {
                    const uint4 xv = xb[(g + 8 * t) * 36 + entry];
                    mma_f16(acc[0][t], A00, A01, A02, A03, xv.x, xv.y);
                    mma_f16(acc[0][t], A00, A01, A02, A03, xv.z, xv.w);
                    mma_f16(acc[1][t], A10, A11, A12, A13, xv.x, xv.y);
                    mma_f16(acc[1][t], A10, A11, A12, A13, xv.z, xv.w);
                }

                #pragma unroll
                for (int j = 0; j < 4; ++j) cw[j] = cwN[j];
            }

            // store prefetched x into the other buffer, then sync
            if (more) {
                uint4* db = xs + (nexthalf & 1) * XSTG_U4;
                #pragma unroll
                for (int j = 0; j < 4; ++j)
                    db[(w + 8 * j) * 36 + lane] = split_x4(xr[j]);
            }
            __syncthreads();
        }
    }

    // ---- final flush ----
    #pragma unroll
    for (int h = 0; h < 2; ++h) {
        const int o0 = cur_tile * TROWS + rowsub + 16 * h;
        #pragma unroll
        for (int t = 0; t < 4; ++t) {
            const int n0 = 8 * t + 2 * q;
            atomicAdd(&out[(size_t)n0 * POUT + o0],           sc * acc[h][t][0]);
            atomicAdd(&out[(size_t)(n0 + 1) * POUT + o0],     sc * acc[h][t][1]);
            atomicAdd(&out[(size_t)n0 * POUT + o0 + 8],       sc * acc[h][t][2]);
            atomicAdd(&out[(size_t)(n0 + 1) * POUT + o0 + 8], sc * acc[h][t][3]);
        }
    }
}

extern "C" void kernel_launch(void* const* d_in, const int* in_sizes, int n_in,
                              void* d_out, int out_size) {
    const float* x = nullptr;
    const float* lut = nullptr;
    const float* bias = nullptr;
    const int*   widx = nullptr;
    for (int i = 0; i < n_in; ++i) {
        if (in_sizes[i] == PB * PIN)            x    = (const float*)d_in[i];
        else if (in_sizes[i] == 256)            lut  = (const float*)d_in[i];
        else if (in_sizes[i] == POUT)           bias = (const float*)d_in[i];
        else                                    widx = (const int*)d_in[i];
    }
    float* out = (float*)d_out;

    cudaFuncSetAttribute(linear_int8_mma_kernel,
                         cudaFuncAttributeMaxDynamicSharedMemorySize, SMEM_BYTES);
    prep_out_kernel<<<4 * PB, 256>>>(x, lut, bias, out);
    linear_int8_mma_kernel<<<NCTA, NTHREADS, SMEM_BYTES>>>(x, lut, bias, widx, out);
}

// round 13
// speedup vs baseline: 1.2659x; 1.2659x over previous
#include <cuda_runtime.h>
#include <cuda_fp16.h>
#include <cstdint>

// ---------------------------------------------------------------------------
// y[b,o] = sum_i x[b,i] * lut[widx[o,i]] + bias[o]
//   B=32, IN=8192, OUT=16384 ; lut affine: lut[c] = lut[0] + c*(lut[1]-lut[0])
//
// Exact-precision fp16 MMA scheme (validated R3..R11):
//   A = (idx-128) exact in fp16 via (0x6400|idx) -> 1024+idx, HSUB2 1152.
//   x = x_hi + x_lo fp16 split; 2x mma.m16n8k16.f16, fp32 accum.
//   out preinit = bias[o] + c0*sumx[b]; GEMM adds sc*acc atomically.
//
// R13: k-major work flattening (unit = kchunk*64 + tile). A CTA's ~7
// consecutive units share the same x k-slice (<=2 distinct kchunks/CTA), so
// x is staged ~twice per CTA into a single buffer and the mainloop runs with
// ~4 __syncthreads total (vs 14 in R11): W staging is per-thread-private
// cp.async, so warps drift freely across the whole CTA range. Accumulator
// flushes per unit via RED.ADD (atomics validated R7+). SMEM 98KB -> still
// 2 CTAs/SM. W transport (cp.async.cg 16B + L2::256B, 4 k16 slots, 64B row
// stride conflict-free) identical to R11. R12's direct-LDG W path is
// abandoned (8-wavefront/instr l1tex cost re-exposed latency).
// ---------------------------------------------------------------------------

#define PB       32
#define PIN      8192
#define POUT     16384
#define NTHREADS 256
#define NCTA     296                      // 2 CTAs per SM
#define TROWS    256                      // rows per tile
#define NTILES   64
#define NKCH     32
#define NUNIT    (NKCH * NTILES)          // 2048, k-major: u = kc*64 + tile
#define EPC      68                       // uint4 entries per x batch row
#define SM_W     (PB * EPC * 16)          // 34816 : W staging base (1KB-aligned)
#define WSLOT    16384u                   // k16 grp: 256 rows * 64B
#define SMEM_BYTES (SM_W + 4 * WSLOT)     // 100352 -> 2 CTAs/SM

__device__ __forceinline__ uint32_t smem_u32(const void* p) {
    uint32_t a;
    asm("{ .reg .u64 t; cvta.to.shared.u64 t, %1; cvt.u32.u64 %0, t; }" : "=r"(a) : "l"(p));
    return a;
}

__device__ __forceinline__ void cpasync16(uint32_t dst, const void* src) {
    asm volatile("cp.async.cg.shared.global.L2::256B [%0], [%1], 16;"
                 :: "r"(dst), "l"(src) : "memory");
}
#define CP_COMMIT() asm volatile("cp.async.commit_group;" ::: "memory")
#define CP_WAIT(n)  asm volatile("cp.async.wait_group %0;" :: "n"(n) : "memory")

#define LDS128(r0, r1, r2, r3, addr)                                  \
    asm volatile("ld.shared.v4.b32 {%0,%1,%2,%3}, [%4];"              \
                 : "=r"(r0), "=r"(r1), "=r"(r2), "=r"(r3) : "r"(addr))

__device__ __forceinline__ void mma_f16(float* c,
                                        uint32_t a0, uint32_t a1, uint32_t a2, uint32_t a3,
                                        uint32_t b0, uint32_t b1) {
    asm volatile(
        "mma.sync.aligned.m16n8k16.row.col.f32.f16.f16.f32 "
        "{%0,%1,%2,%3}, {%4,%5,%6,%7}, {%8,%9}, {%0,%1,%2,%3};"
        : "+f"(c[0]), "+f"(c[1]), "+f"(c[2]), "+f"(c[3])
        : "r"(a0), "r"(a1), "r"(a2), "r"(a3), "r"(b0), "r"(b1));
}

// two int8 codes -> packed half2 of EXACT (idx-128)
__device__ __forceinline__ uint32_t packA(uint32_t i0, uint32_t i1, uint32_t off2) {
    uint32_t r = 0x64006400u | i0 | (i1 << 16);
    __half2 h = __hsub2(*reinterpret_cast<__half2*>(&r),
                        *reinterpret_cast<const __half2*>(&off2));
    return *reinterpret_cast<uint32_t*>(&h);
}

__device__ __forceinline__ uint4 split_x4(float4 v) {
    __half2 h0 = __floats2half2_rn(v.x, v.y);
    __half2 h1 = __floats2half2_rn(v.z, v.w);
    float2 f0 = __half22float2(h0);
    float2 f1 = __half22float2(h1);
    __half2 l0 = __floats2half2_rn(v.x - f0.x, v.y - f0.y);
    __half2 l1 = __floats2half2_rn(v.z - f1.x, v.w - f1.y);
    uint4 s;
    s.x = *reinterpret_cast<uint32_t*>(&h0);
    s.y = *reinterpret_cast<uint32_t*>(&h1);
    s.z = *reinterpret_cast<uint32_t*>(&l0);
    s.w = *reinterpret_cast<uint32_t*>(&l1);
    return s;
}

// ---- fused prep: out[b, o] = bias[o] + c0*sumx[b] (grid = 4*PB) ----
__global__ void prep_out_kernel(const float* __restrict__ x,
                                const float* __restrict__ lut,
                                const float* __restrict__ bias,
                                float* __restrict__ out) {
    __shared__ float red[8];
    const int b       = blockIdx.x >> 2;
    const int quarter = blockIdx.x & 3;

    const float4* xr = reinterpret_cast<const float4*>(x + (size_t)b * PIN);
    float s = 0.0f;
    #pragma unroll
    for (int j = 0; j < (PIN / 4) / 256; ++j) {
        float4 v = __ldg(xr + threadIdx.x + 256 * j);
        s += (v.x + v.y) + (v.z + v.w);
    }
    #pragma unroll
    for (int o = 16; o; o >>= 1) s += __shfl_xor_sync(0xFFFFFFFFu, s, o);
    if ((threadIdx.x & 31) == 0) red[threadIdx.x >> 5] = s;
    __syncthreads();
    {
        float t = red[0];
        #pragma unroll
        for (int k = 1; k < 8; ++k) t += red[k];
        s = t;                                             // deterministic order
    }

    const float l0 = __ldg(lut);
    const float sc = __ldg(lut + 1) - l0;
    const float c0 = fmaf(128.0f, sc, l0);
    const float addv = c0 * s;

    const int obase = quarter * (POUT / 4);
    const float4* bq = reinterpret_cast<const float4*>(bias + obase);
    float4* oq = reinterpret_cast<float4*>(out + (size_t)b * POUT + obase);
    #pragma unroll
    for (int j = 0; j < (POUT / 4) / 4 / 256; ++j) {
        float4 bv = __ldg(bq + threadIdx.x + 256 * j);
        bv.x += addv; bv.y += addv; bv.z += addv; bv.w += addv;
        oq[threadIdx.x + 256 * j] = bv;
    }
}

__global__ void __launch_bounds__(NTHREADS, 2)
linear_int8_mma_kernel(const float* __restrict__ x,
                       const float* __restrict__ lut,
                       const float* __restrict__ bias,
                       const int*   __restrict__ widx,
                       float*       __restrict__ out) {
    extern __shared__ __align__(16) uint4 xs[];   // x: 32 x 68 uint4 ; W after
    const uint32_t sbase = smem_u32(xs);

    const int tid  = threadIdx.x;
    const int w    = tid >> 5;
    const int lane = tid & 31;
    const int g    = lane >> 2;       // fragment group: A row / B col
    const int q    = lane & 3;        // fragment k-slot

    const float l0 = __ldg(lut);
    const float sc = __ldg(lut + 1) - l0;
    const uint32_t off1152 = 0x64806480u;   // half2(1152,1152)

    // ---- this CTA's flat unit range [s, e): u = kc*NTILES + tile ----
    const int s = (int)(((unsigned)blockIdx.x * NUNIT) / NCTA);
    const int e = (int)((((unsigned)blockIdx.x + 1) * NUNIT) / NCTA);
    const int gEnd = e * 16;                   // k16-grp end

    // warp covers rows rowsub + {0,8,16,24} of a 256-row tile
    const int rowsub = w * 32 + g;
    const char* wr0 = reinterpret_cast<const char*>(widx)
                      + (size_t)rowsub * PIN * 4 + (size_t)q * 16;
    const size_t TILESTRIDE = (size_t)TROWS * PIN * 4;    // 8MB per tile
    const size_t J8 = (size_t)8 * PIN * 4;                // +8 rows

    // W address of k16-grp gg for this thread's base row
    auto waddr = [&](int gg) -> const char* {
        const int u    = gg >> 4;
        const int st   = gg & 15;
        const int kc   = u >> 6;
        const int tile = u & (NTILES - 1);
        return wr0 + (size_t)tile * TILESTRIDE + (size_t)(kc * 16 + st) * 64;
    };

    // thread's W smem address (64B row stride, own copies, conflict-free)
    const uint32_t wsl_thr = sbase + SM_W + (uint32_t)rowsub * 64u + (uint32_t)q * 16u;

    float acc[2][4][4];
    #pragma unroll
    for (int h = 0; h < 2; ++h)
        #pragma unroll
        for (int t = 0; t < 4; ++t)
            #pragma unroll
            for (int i = 0; i < 4; ++i) acc[h][t][i] = 0.0f;

    // ---- prologue: issue W k16-grps s*16 .. +3 into slots 0..3 ----
    #pragma unroll
    for (int sidx = 0; sidx < 4; ++sidx) {
        const int gg = s * 16 + sidx;
        const char* p = waddr(gg);
        const uint32_t ds = wsl_thr + (uint32_t)(gg & 3) * WSLOT;
        #pragma unroll
        for (int j = 0; j < 4; ++j) cpasync16(ds + (uint32_t)j * 512u, p + (size_t)j * J8);
        CP_COMMIT();
    }

    const float4* xg = reinterpret_cast<const float4*>(x);
    int cur_kc = -1;

    for (int u = s; u < e; ++u) {
        const int kc   = u >> 6;
        const int tile = u & (NTILES - 1);

        // ---- (re)stage x when the k-chunk changes (<=2 times per CTA) ----
        if (kc != cur_kc) {
            __syncthreads();                      // old-buffer readers done
            #pragma unroll
            for (int j = 0; j < 8; ++j) {
                const int f  = tid + 256 * j;
                const int n  = f >> 6;
                const int kg = f & 63;
                float4 v = __ldg(xg + (size_t)n * (PIN / 4) + kc * 64 + kg);
                xs[n * EPC + kg] = split_x4(v);
            }
            __syncthreads();
            cur_kc = kc;
        }

        #pragma unroll
        for (int st = 0; st < 16; ++st) {
            const int gg = u * 16 + st;
            const int rem = gEnd - gg;
            if (rem > 3)       { CP_WAIT(3); }
            else if (rem == 3) { CP_WAIT(2); }
            else if (rem == 2) { CP_WAIT(1); }
            else               { CP_WAIT(0); }

            // ---- W readback: 4 rows x k16 (conflict-free, 64B stride) ----
            const uint32_t rb = wsl_thr + (uint32_t)(gg & 3) * WSLOT;
            uint4 cw[4];
            #pragma unroll
            for (int j = 0; j < 4; ++j)
                LDS128(cw[j].x, cw[j].y, cw[j].z, cw[j].w, rb + (uint32_t)j * 512u);

            // ---- refill this slot with grp gg+4 ----
            if (gg + 4 < gEnd) {
                const char* p = waddr(gg + 4);
                #pragma unroll
                for (int j = 0; j < 4; ++j)
                    cpasync16(rb + (uint32_t)j * 512u, p + (size_t)j * J8);
                CP_COMMIT();
            }

            // ---- dequant ----
            const uint32_t A00 = packA(cw[0].x, cw[0].y, off1152);
            const uint32_t A02 = packA(cw[0].z, cw[0].w, off1152);
            const uint32_t A01 = packA(cw[1].x, cw[1].y, off1152);
            const uint32_t A03 = packA(cw[1].z, cw[1].w, off1152);
            const uint32_t A10 = packA(cw[2].x, cw[2].y, off1152);
            const uint32_t A12 = packA(cw[2].z, cw[2].w, off1152);
            const uint32_t A11 = packA(cw[3].x, cw[3].y, off1152);
            const uint32_t A13 = packA(cw[3].z, cw[3].w, off1152);

            // ---- x fragments + MMA (x shared by both m16 tiles) ----
            const int entry = st * 4 + q;
            #pragma unroll
            for (int t = 0; t < 4; ++t) {
                const uint4 xv = xs[(g + 8 * t) * EPC + entry];
                mma_f16(acc[0][t], A00, A01, A02, A03, xv.x, xv.y);
                mma_f16(acc[0][t], A00, A01, A02, A03, xv.z, xv.w);
                mma_f16(acc[1][t], A10, A11, A12, A13, xv.x, xv.y);
                mma_f16(acc[1][t], A10, A11, A12, A13, xv.z, xv.w);
            }
        }

        // ---- per-unit flush (RED.ADD, no barrier needed) ----
        #pragma unroll
        for (int h = 0; h < 2; ++h) {
            const int o0 = tile * TROWS + rowsub + 16 * h;
            #pragma unroll
            for (int t = 0; t < 4; ++t) {
                const int n0 = 8 * t + 2 * q;
                atomicAdd(&out[(size_t)n0 * POUT + o0],           sc * acc[h][t][0]);
                atomicAdd(&out[(size_t)(n0 + 1) * POUT + o0],     sc * acc[h][t][1]);
                atomicAdd(&out[(size_t)n0 * POUT + o0 + 8],       sc * acc[h][t][2]);
                atomicAdd(&out[(size_t)(n0 + 1) * POUT + o0 + 8], sc * acc[h][t][3]);
                acc[h][t][0] = acc[h][t][1] = acc[h][t][2] = acc[h][t][3] = 0.0f;
            }
        }
    }
}

extern "C" void kernel_launch(void* const* d_in, const int* in_sizes, int n_in,
                              void* d_out, int out_size) {
    const float* x = nullptr;
    const float* lut = nullptr;
    const float* bias = nullptr;
    const int*   widx = nullptr;
    for (int i = 0; i < n_in; ++i) {
        if (in_sizes[i] == PB * PIN)            x    = (const float*)d_in[i];
        else if (in_sizes[i] == 256)            lut  = (const float*)d_in[i];
        else if (in_sizes[i] == POUT)           bias = (const float*)d_in[i];
        else                                    widx = (const int*)d_in[i];
    }
    float* out = (float*)d_out;

    cudaFuncSetAttribute(linear_int8_mma_kernel,
                         cudaFuncAttributeMaxDynamicSharedMemorySize, SMEM_BYTES);
    prep_out_kernel<<<4 * PB, 256>>>(x, lut, bias, out);
    linear_int8_mma_kernel<<<NCTA, NTHREADS, SMEM_BYTES>>>(x, lut, bias, widx, out);
}

// round 14
// speedup vs baseline: 1.2873x; 1.0169x over previous
#include <cuda_runtime.h>
#include <cuda_fp16.h>
#include <cstdint>

// ---------------------------------------------------------------------------
// y[b,o] = sum_i x[b,i] * lut[widx[o,i]] + bias[o]
//   B=32, IN=8192, OUT=16384 ; lut affine: lut[c] = lut[0] + c*(lut[1]-lut[0])
//
// Exact-precision fp16 MMA scheme (validated R3..R13):
//   A = (idx-128) exact in fp16 via (0x6400|idx) -> 1024+idx, HSUB2 1152.
//   x = x_hi + x_lo fp16 split; 2x mma.m16n8k16.f16, fp32 accum.
//   out preinit = bias[o] + c0*sumx[b]; GEMM adds sc*acc atomically.
//
// R14 = R11 (best, 90.6us) + depth-5 W pipeline:
//   * W: 5 slots x 16KB k16-grps (rotating mod-5 slot counter), per-thread
//     cp.async.cg 16B + L2::256B, 64B row stride (conflict-free readback).
//   * x: k64 stages, 2 x (32 rows x 20-uint4 pitch) = 20.5KB; pitch = 80
//     words = 16 mod 32 -> conflict-free STS and fragment LDS.
//   * SMEM 100KB -> 2 CTAs/SM kept. Tile-major persistent 296 CTAs,
//     atomic flush + fused prep unchanged (R13's k-major flush storm
//     reverted).
// ---------------------------------------------------------------------------

#define PB       32
#define PIN      8192
#define POUT     16384
#define NTHREADS 256
#define NCTA     296                      // 2 CTAs per SM
#define TROWS    256                      // rows per tile
#define NUNIT    2048                     // 64 tiles * 32 k256-chunks
#define NSLOT    5
#define XPITCH   20                       // uint4 per x batch row (16 + 4 pad)
#define XSTG_U4  (PB * XPITCH)            // 640 uint4 per k64 stage
#define SM_W     (2 * XSTG_U4 * 16)       // 20480 : W staging base
#define WSLOT    16384u                   // k16 grp: 256 rows * 64B
#define SMEM_BYTES (SM_W + NSLOT * WSLOT) // 102400 -> 2 CTAs/SM

__device__ __forceinline__ uint32_t smem_u32(const void* p) {
    uint32_t a;
    asm("{ .reg .u64 t; cvta.to.shared.u64 t, %1; cvt.u32.u64 %0, t; }" : "=r"(a) : "l"(p));
    return a;
}

__device__ __forceinline__ void cpasync16(uint32_t dst, const void* src) {
    asm volatile("cp.async.cg.shared.global.L2::256B [%0], [%1], 16;"
                 :: "r"(dst), "l"(src) : "memory");
}
#define CP_COMMIT() asm volatile("cp.async.commit_group;" ::: "memory")
#define CP_WAIT(n)  asm volatile("cp.async.wait_group %0;" :: "n"(n) : "memory")

#define LDS128(r0, r1, r2, r3, addr)                                  \
    asm volatile("ld.shared.v4.b32 {%0,%1,%2,%3}, [%4];"              \
                 : "=r"(r0), "=r"(r1), "=r"(r2), "=r"(r3) : "r"(addr))

__device__ __forceinline__ void mma_f16(float* c,
                                        uint32_t a0, uint32_t a1, uint32_t a2, uint32_t a3,
                                        uint32_t b0, uint32_t b1) {
    asm volatile(
        "mma.sync.aligned.m16n8k16.row.col.f32.f16.f16.f32 "
        "{%0,%1,%2,%3}, {%4,%5,%6,%7}, {%8,%9}, {%0,%1,%2,%3};"
        : "+f"(c[0]), "+f"(c[1]), "+f"(c[2]), "+f"(c[3])
        : "r"(a0), "r"(a1), "r"(a2), "r"(a3), "r"(b0), "r"(b1));
}

// two int8 codes -> packed half2 of EXACT (idx-128)
__device__ __forceinline__ uint32_t packA(uint32_t i0, uint32_t i1, uint32_t off2) {
    uint32_t r = 0x64006400u | i0 | (i1 << 16);
    __half2 h = __hsub2(*reinterpret_cast<__half2*>(&r),
                        *reinterpret_cast<const __half2*>(&off2));
    return *reinterpret_cast<uint32_t*>(&h);
}

__device__ __forceinline__ uint4 split_x4(float4 v) {
    __half2 h0 = __floats2half2_rn(v.x, v.y);
    __half2 h1 = __floats2half2_rn(v.z, v.w);
    float2 f0 = __half22float2(h0);
    float2 f1 = __half22float2(h1);
    __half2 l0 = __floats2half2_rn(v.x - f0.x, v.y - f0.y);
    __half2 l1 = __floats2half2_rn(v.z - f1.x, v.w - f1.y);
    uint4 s;
    s.x = *reinterpret_cast<uint32_t*>(&h0);
    s.y = *reinterpret_cast<uint32_t*>(&h1);
    s.z = *reinterpret_cast<uint32_t*>(&l0);
    s.w = *reinterpret_cast<uint32_t*>(&l1);
    return s;
}

// ---- fused prep: out[b, o] = bias[o] + c0*sumx[b] (grid = 4*PB) ----
__global__ void prep_out_kernel(const float* __restrict__ x,
                                const float* __restrict__ lut,
                                const float* __restrict__ bias,
                                float* __restrict__ out) {
    __shared__ float red[8];
    const int b       = blockIdx.x >> 2;
    const int quarter = blockIdx.x & 3;

    const float4* xr = reinterpret_cast<const float4*>(x + (size_t)b * PIN);
    float s = 0.0f;
    #pragma unroll
    for (int j = 0; j < (PIN / 4) / 256; ++j) {
        float4 v = __ldg(xr + threadIdx.x + 256 * j);
        s += (v.x + v.y) + (v.z + v.w);
    }
    #pragma unroll
    for (int o = 16; o; o >>= 1) s += __shfl_xor_sync(0xFFFFFFFFu, s, o);
    if ((threadIdx.x & 31) == 0) red[threadIdx.x >> 5] = s;
    __syncthreads();
    {
        float t = red[0];
        #pragma unroll
        for (int k = 1; k < 8; ++k) t += red[k];
        s = t;                                             // deterministic order
    }

    const float l0 = __ldg(lut);
    const float sc = __ldg(lut + 1) - l0;
    const float c0 = fmaf(128.0f, sc, l0);
    const float addv = c0 * s;

    const int obase = quarter * (POUT / 4);
    const float4* bq = reinterpret_cast<const float4*>(bias + obase);
    float4* oq = reinterpret_cast<float4*>(out + (size_t)b * POUT + obase);
    #pragma unroll
    for (int j = 0; j < (POUT / 4) / 4 / 256; ++j) {
        float4 bv = __ldg(bq + threadIdx.x + 256 * j);
        bv.x += addv; bv.y += addv; bv.z += addv; bv.w += addv;
        oq[threadIdx.x + 256 * j] = bv;
    }
}

__global__ void __launch_bounds__(NTHREADS, 2)
linear_int8_mma_kernel(const float* __restrict__ x,
                       const float* __restrict__ lut,
                       const float* __restrict__ bias,
                       const int*   __restrict__ widx,
                       float*       __restrict__ out) {
    extern __shared__ __align__(16) uint4 xs[];   // x: 2 x 640 uint4 ; W after
    const uint32_t sbase = smem_u32(xs);

    const int tid  = threadIdx.x;
    const int w    = tid >> 5;
    const int lane = tid & 31;
    const int g    = lane >> 2;       // fragment group: A row / B col
    const int q    = lane & 3;        // fragment k-slot

    const float l0 = __ldg(lut);
    const float sc = __ldg(lut + 1) - l0;
    const uint32_t off1152 = 0x64806480u;   // half2(1152,1152)

    // ---- this CTA's flat k256-chunk range [s, e), tile-major ----
    const int s = (int)(((unsigned)blockIdx.x * NUNIT) / NCTA);
    const int e = (int)((((unsigned)blockIdx.x + 1) * NUNIT) / NCTA);
    const int gEnd = e * 16;                   // k16-grp end

    // warp covers rows rowsub + {0,8,16,24} of the 256-row tile
    const int rowsub = w * 32 + g;
    const char* wr0 = reinterpret_cast<const char*>(widx)
                      + (size_t)rowsub * PIN * 4 + (size_t)q * 16;
    const size_t TILESTRIDE = (size_t)TROWS * PIN * 4;    // 8MB per tile
    const size_t J8 = (size_t)8 * PIN * 4;                // +8 rows

    // W address of k16-grp gg for this thread's base row
    auto waddr = [&](int gg) -> const char* {
        const int cu  = gg >> 4;
        const int k16 = (cu & 31) * 16 + (gg & 15);
        return wr0 + (size_t)(cu >> 5) * TILESTRIDE + (size_t)k16 * 64;
    };

    // thread's W smem address (64B row stride, own copies, conflict-free)
    const uint32_t wsl_thr = sbase + SM_W + (uint32_t)rowsub * 64u + (uint32_t)q * 16u;

    float acc[2][4][4];
    #pragma unroll
    for (int h = 0; h < 2; ++h)
        #pragma unroll
        for (int t = 0; t < 4; ++t)
            #pragma unroll
            for (int i = 0; i < 4; ++i) acc[h][t][i] = 0.0f;

    const int gStart = s * 16;

    // ---- prologue: issue W grps gStart..gStart+4 into slots 0..4 ----
    #pragma unroll
    for (int sidx = 0; sidx < NSLOT; ++sidx) {
        const char* p = waddr(gStart + sidx);
        const uint32_t ds = wsl_thr + (uint32_t)sidx * WSLOT;
        #pragma unroll
        for (int j = 0; j < 4; ++j) cpasync16(ds + (uint32_t)j * 512u, p + (size_t)j * J8);
        CP_COMMIT();
    }

    // ---- stage x: k64 half 0 of chunk s ----
    const float4* xg = reinterpret_cast<const float4*>(x);
    float4 xr[2];
    {
        const int kb4 = (s & 31) * 64;             // float4 base of chunk
        #pragma unroll
        for (int j = 0; j < 2; ++j) {
            const int f = tid + 256 * j;           // 0..511
            const int n = f >> 4, kg = f & 15;
            xr[j] = __ldg(xg + (size_t)n * (PIN / 4) + kb4 + kg);
        }
        uint4* db = xs;                            // stage 0
        #pragma unroll
        for (int j = 0; j < 2; ++j) {
            const int f = tid + 256 * j;
            const int n = f >> 4, kg = f & 15;
            db[n * XPITCH + kg] = split_x4(xr[j]);
        }
    }
    __syncthreads();

    int cur_tile = s >> 5;
    int cslot = 0;                                 // rotating slot of current grp

    for (int c = s; c < e; ++c) {
        const int t_tile = c >> 5;
        if (t_tile != cur_tile) {
            #pragma unroll
            for (int h = 0; h < 2; ++h) {
                const int o0 = cur_tile * TROWS + rowsub + 16 * h;
                #pragma unroll
                for (int t = 0; t < 4; ++t) {
                    const int n0 = 8 * t + 2 * q;
                    atomicAdd(&out[(size_t)n0 * POUT + o0],           sc * acc[h][t][0]);
                    atomicAdd(&out[(size_t)(n0 + 1) * POUT + o0],     sc * acc[h][t][1]);
                    atomicAdd(&out[(size_t)n0 * POUT + o0 + 8],       sc * acc[h][t][2]);
                    atomicAdd(&out[(size_t)(n0 + 1) * POUT + o0 + 8], sc * acc[h][t][3]);
                    acc[h][t][0] = acc[h][t][1] = acc[h][t][2] = acc[h][t][3] = 0.0f;
                }
            }
            cur_tile = t_tile;
        }

        #pragma unroll
        for (int hf = 0; hf < 4; ++hf) {           // four k64 halves per chunk
            const int ghalf = c * 4 + hf;          // global half index
            const uint4* xb = xs + (ghalf & 1) * XSTG_U4;

            // prefetch next k64 half of x into registers
            const int nh = ghalf + 1;
            const bool more = nh < e * 4;
            if (more) {
                const int cn = nh >> 2, hn = nh & 3;
                const int kb4 = (cn & 31) * 64 + hn * 16;
                #pragma unroll
                for (int j = 0; j < 2; ++j) {
                    const int f = tid + 256 * j;
                    const int n = f >> 4, kg = f & 15;
                    xr[j] = __ldg(xg + (size_t)n * (PIN / 4) + kb4 + kg);
                }
            }

            #pragma unroll
            for (int st = 0; st < 4; ++st) {
                const int gg = c * 16 + hf * 4 + st;
                const int rem = gEnd - gg;
                if (rem > 4)       { CP_WAIT(4); }
                else if (rem == 4) { CP_WAIT(3); }
                else if (rem == 3) { CP_WAIT(2); }
                else if (rem == 2) { CP_WAIT(1); }
                else               { CP_WAIT(0); }

                // ---- W readback: 4 rows x k16 (conflict-free, 64B stride) ----
                const uint32_t rb = wsl_thr + (uint32_t)cslot * WSLOT;
                uint4 cw[4];
                #pragma unroll
                for (int j = 0; j < 4; ++j)
                    LDS128(cw[j].x, cw[j].y, cw[j].z, cw[j].w, rb + (uint32_t)j * 512u);

                // ---- refill freed slot with grp gg+NSLOT ----
                if (gg + NSLOT < gEnd) {
                    const char* p = waddr(gg + NSLOT);
                    #pragma unroll
                    for (int j = 0; j < 4; ++j)
                        cpasync16(rb + (uint32_t)j * 512u, p + (size_t)j * J8);
                    CP_COMMIT();
                }
                cslot = (cslot == NSLOT - 1) ? 0 : cslot + 1;

                // ---- dequant ----
                const uint32_t A00 = packA(cw[0].x, cw[0].y, off1152);
                const uint32_t A02 = packA(cw[0].z, cw[0].w, off1152);
                const uint32_t A01 = packA(cw[1].x, cw[1].y, off1152);
                const uint32_t A03 = packA(cw[1].z, cw[1].w, off1152);
                const uint32_t A10 = packA(cw[2].x, cw[2].y, off1152);
                const uint32_t A12 = packA(cw[2].z, cw[2].w, off1152);
                const uint32_t A11 = packA(cw[3].x, cw[3].y, off1152);
                const uint32_t A13 = packA(cw[3].z, cw[3].w, off1152);

                // ---- x fragments + MMA (x shared by both m16 tiles) ----
                const int entry = st * 4 + q;
                #pragma unroll
                for (int t = 0; t < 4; ++t) {
                    const uint4 xv = xb[(g + 8 * t) * XPITCH + entry];
                    mma_f16(acc[0][t], A00, A01, A02, A03, xv.x, xv.y);
                    mma_f16(acc[0][t], A00, A01, A02, A03, xv.z, xv.w);
                    mma_f16(acc[1][t], A10, A11, A12, A13, xv.x, xv.y);
                    mma_f16(acc[1][t], A10, A11, A12, A13, xv.z, xv.w);
                }
            }

            // store prefetched x into the other stage, then sync
            if (more) {
                uint4* db = xs + ((ghalf + 1) & 1) * XSTG_U4;
                #pragma unroll
                for (int j = 0; j < 2; ++j) {
                    const int f = tid + 256 * j;
                    const int n = f >> 4, kg = f & 15;
                    db[n * XPITCH + kg] = split_x4(xr[j]);
                }
            }
            __syncthreads();
        }
    }

    // ---- final flush ----
    #pragma unroll
    for (int h = 0; h < 2; ++h) {
        const int o0 = cur_tile * TROWS + rowsub + 16 * h;
        #pragma unroll
        for (int t = 0; t < 4; ++t) {
            const int n0 = 8 * t + 2 * q;
            atomicAdd(&out[(size_t)n0 * POUT + o0],           sc * acc[h][t][0]);
            atomicAdd(&out[(size_t)(n0 + 1) * POUT + o0],     sc * acc[h][t][1]);
            atomicAdd(&out[(size_t)n0 * POUT + o0 + 8],       sc * acc[h][t][2]);
            atomicAdd(&out[(size_t)(n0 + 1) * POUT + o0 + 8], sc * acc[h][t][3]);
        }
    }
}

extern "C" void kernel_launch(void* const* d_in, const int* in_sizes, int n_in,
                              void* d_out, int out_size) {
    const float* x = nullptr;
    const float* lut = nullptr;
    const float* bias = nullptr;
    const int*   widx = nullptr;
    for (int i = 0; i < n_in; ++i) {
        if (in_sizes[i] == PB * PIN)            x    = (const float*)d_in[i];
        else if (in_sizes[i] == 256)            lut  = (const float*)d_in[i];
        else if (in_sizes[i] == POUT)           bias = (const float*)d_in[i];
        else                                    widx = (const int*)d_in[i];
    }
    float* out = (float*)d_out;

    cudaFuncSetAttribute(linear_int8_mma_kernel,
                         cudaFuncAttributeMaxDynamicSharedMemorySize, SMEM_BYTES);
    prep_out_kernel<<<4 * PB, 256>>>(x, lut, bias, out);
    linear_int8_mma_kernel<<<NCTA, NTHREADS, SMEM_BYTES>>>(x, lut, bias, widx, out);
}